// round 14
// baseline (speedup 1.0000x reference)
#include <cuda_runtime.h>
#include <cuda_fp16.h>
#include <math.h>
#include <stdint.h>

#define NA 50000
#define NP 50000
#define EE 600000
#define HH 8
#define DD 16
#define CC 128
#define OUTC 16
#define FA 256
#define FP 128
#define EPSV 1e-5f

// ---------------- device scratch ----------------
__device__ __half   g_h_a[(size_t)NA * CC];
__device__ __half   g_h_p[(size_t)NP * CC];
__device__ float    g_as_ap[NA * HH];
__device__ float    g_ad_ap[NP * HH];
__device__ float    g_as_pp[NP * HH];
__device__ float    g_ad_pp[NP * HH];
__device__ int      g_cnt[2 * NP];
__device__ int      g_rank[2 * (size_t)EE];
__device__ int      g_rowptr[2 * (NP + 1)];
__device__ int      g_srcs[2 * (size_t)EE];
__device__ __half   g_out01[2 * (size_t)NP * CC]; // fp16, relu-applied
__device__ __half   g_Wah[FA * CC];
__device__ __half   g_Wph[FP * CC];
__device__ __half   g_kWh[CC * CC];
__device__ float    g_wsum[2];
__device__ float    g_Sa[CC], g_Sb[CC], g_Saa[CC], g_Sbb[CC], g_Sab[CC];

// ---------------- helpers ----------------
__device__ __forceinline__ float tanh_fast(float x) {
    float y;
    asm("tanh.approx.f32 %0, %1;" : "=f"(y) : "f"(x));
    return y;
}
__device__ __forceinline__ uint32_t packh2(float lo, float hi) {
    __half2 h = __float22half2_rn(make_float2(lo, hi));
    return *(uint32_t*)&h;
}
__device__ __forceinline__ void mma_f16(float* c, const uint32_t* a,
                                        uint32_t b0, uint32_t b1) {
    asm("mma.sync.aligned.m16n8k16.row.col.f32.f16.f16.f32 "
        "{%0,%1,%2,%3},{%4,%5,%6,%7},{%8,%9},{%0,%1,%2,%3};"
        : "+f"(c[0]), "+f"(c[1]), "+f"(c[2]), "+f"(c[3])
        : "r"(a[0]), "r"(a[1]), "r"(a[2]), "r"(a[3]), "r"(b0), "r"(b1));
}
__device__ __forceinline__ void cp16(uint32_t dst, const void* src, int sz) {
    asm volatile("cp.async.ca.shared.global [%0], [%1], 16, %2;"
                 :: "r"(dst), "l"(src), "r"(sz));
}
__device__ __forceinline__ void cp_commit() { asm volatile("cp.async.commit_group;"); }
__device__ __forceinline__ void cp_wait1()  { asm volatile("cp.async.wait_group 1;"); }

#define APITCH 20
#define ASTAGE_FLOATS (128 * APITCH)
#define ASTAGE_BYTES  (ASTAGE_FLOATS * 4)
#define AH_PITCH 24
#define AH_STAGE  (128 * AH_PITCH)
#define AH_STAGE_BYTES (AH_STAGE * 2)
#define BSTAGE_H      2048
#define BSTAGE_BYTES  (BSTAGE_H * 2)

// grid partition constants
#define GA 391
#define GP 391
#define GH 1024
#define GSEM 782
#define GST 98

// ---------------- init ----------------
__device__ __forceinline__ void build_wh(const float* __restrict__ W,
                                         __half* __restrict__ Wh,
                                         int total, int idx, int stride) {
    for (int o = idx; o < total; o += stride) {
        int kt = o >> 11;
        int rem = o & 2047;
        int col = rem >> 4;
        int u = rem & 15;
        int t4 = u >> 2;
        int j = u & 3;
        int k = kt * 16 + 2 * t4 + (j & 1) + 8 * (j >> 1);
        Wh[o] = __float2half_rn(W[k * CC + col]);
    }
}

__global__ void init_kernel(const float* __restrict__ Wa,
                            const float* __restrict__ Wp,
                            const float* __restrict__ kW) {
    int idx = blockIdx.x * blockDim.x + threadIdx.x;
    int stride = gridDim.x * blockDim.x;
    for (int i = idx; i < 2 * NP; i += stride) g_cnt[i] = 0;
    build_wh(Wa, g_Wah, FA * CC, idx, stride);
    build_wh(Wp, g_Wph, FP * CC, idx, stride);
    build_wh(kW, g_kWh, CC * CC, idx, stride);
    if (idx < CC) {
        g_Sa[idx] = 0.f; g_Sb[idx] = 0.f;
        g_Saa[idx] = 0.f; g_Sbb[idx] = 0.f; g_Sab[idx] = 0.f;
    }
    if (idx < 2) g_wsum[idx] = 0.f;
}

// ---------------- alpha epilogue ----------------
__device__ __forceinline__ void alpha_epilogue(
        const float acc[16][4], const float* __restrict__ att,
        float* __restrict__ out, int r1, int r2, int Nrows, int t4) {
    int t2 = t4 * 2;
    float p1[8], p2[8];
#pragma unroll
    for (int h = 0; h < 8; h++) {
        int na = 2 * h, nb = 2 * h + 1;
        float2 aA = *(const float2*)(att + na * 8 + t2);
        float2 aB = *(const float2*)(att + nb * 8 + t2);
        p1[h] = acc[na][0] * aA.x + acc[na][1] * aA.y
              + acc[nb][0] * aB.x + acc[nb][1] * aB.y;
        p2[h] = acc[na][2] * aA.x + acc[na][3] * aA.y
              + acc[nb][2] * aB.x + acc[nb][3] * aB.y;
    }
#pragma unroll
    for (int h = 0; h < 8; h++) {
        p1[h] += __shfl_xor_sync(0xFFFFFFFFu, p1[h], 1);
        p1[h] += __shfl_xor_sync(0xFFFFFFFFu, p1[h], 2);
        p2[h] += __shfl_xor_sync(0xFFFFFFFFu, p2[h], 1);
        p2[h] += __shfl_xor_sync(0xFFFFFFFFu, p2[h], 2);
    }
#pragma unroll
    for (int h = 0; h < 8; h++) {
        if ((h & 3) == t4) {
            if (r1 < Nrows) out[r1 * 8 + h] = p1[h];
            if (r2 < Nrows) out[r2 * 8 + h] = p2[h];
        }
    }
}

// ---------------- fp32-A gemm mainloop (phase1) ----------------
template <int KDIM>
__device__ __forceinline__ void gemm_mainloop(
        const float* __restrict__ abase, int aok,
        const __half* __restrict__ Wh,
        float* As, __half* Bs, float acc[16][4],
        int tid, int w, int g, int t4) {
    const __half* bbase = Wh + tid * 8;
    int arow = tid >> 1, ak = (tid & 1) * 8;
    uint32_t dA0 = (uint32_t)__cvta_generic_to_shared(&As[arow * APITCH + ak]);
    uint32_t dB0 = (uint32_t)__cvta_generic_to_shared(&Bs[tid * 8]);
    const int NT = KDIM / 16;

#pragma unroll
    for (int p = 0; p < 2; p++) {
        const float* ap = abase + p * 16;
        const __half* bp = bbase + (size_t)p * BSTAGE_H;
        uint32_t dA = dA0 + p * ASTAGE_BYTES;
        uint32_t dB = dB0 + p * BSTAGE_BYTES;
        cp16(dA, ap, aok); cp16(dA + 16, ap + 4, aok);
        cp16(dB, bp, 16);
        cp_commit();
    }

    int stage = 0, nstage = 2;
    for (int kt = 0; kt < NT; kt++) {
        cp_wait1();
        __syncthreads();
        if (kt + 2 < NT) {
            const float* ap = abase + (kt + 2) * 16;
            const __half* bp = bbase + (size_t)(kt + 2) * BSTAGE_H;
            uint32_t dA = dA0 + nstage * ASTAGE_BYTES;
            uint32_t dB = dB0 + nstage * BSTAGE_BYTES;
            cp16(dA, ap, aok); cp16(dA + 16, ap + 4, aok);
            cp16(dB, bp, 16);
        }
        cp_commit();

        const float* Ab = As + stage * ASTAGE_FLOATS;
        const __half* Bb = Bs + stage * BSTAGE_H;

        uint32_t afr[4];
        {
            const float* ar1 = Ab + (w * 16 + g) * APITCH;
            const float* ar2 = Ab + (w * 16 + g + 8) * APITCH;
            float2 lo1 = *(const float2*)(ar1 + 2 * t4);
            float2 lo2 = *(const float2*)(ar2 + 2 * t4);
            float2 hi1 = *(const float2*)(ar1 + 2 * t4 + 8);
            float2 hi2 = *(const float2*)(ar2 + 2 * t4 + 8);
            afr[0] = packh2(lo1.x, lo1.y);
            afr[1] = packh2(lo2.x, lo2.y);
            afr[2] = packh2(hi1.x, hi1.y);
            afr[3] = packh2(hi2.x, hi2.y);
        }
#pragma unroll
        for (int nt = 0; nt < 16; nt++) {
            uint2 bq = *(const uint2*)(Bb + (nt * 8 + g) * 16 + t4 * 4);
            mma_f16(acc[nt], afr, bq.x, bq.y);
        }
        stage = (stage + 1 == 3) ? 0 : stage + 1;
        nstage = (nstage + 1 == 3) ? 0 : nstage + 1;
    }
}

// ---------------- fp16-A gemm mainloop (semantic) ----------------
__device__ __forceinline__ void gemm_mainloop_h(
        const __half* __restrict__ abase, int aok,
        const __half* __restrict__ Wh,
        __half* As, __half* Bs, float acc[16][4],
        int tid, int w, int g, int t4) {
    const __half* bbase = Wh + tid * 8;
    int arow = tid >> 1, ak = (tid & 1) * 8;
    uint32_t dA0 = (uint32_t)__cvta_generic_to_shared(&As[arow * AH_PITCH + ak]);
    uint32_t dB0 = (uint32_t)__cvta_generic_to_shared(&Bs[tid * 8]);
    const int NT = CC / 16;

#pragma unroll
    for (int p = 0; p < 2; p++) {
        cp16(dA0 + p * AH_STAGE_BYTES, abase + p * 16, aok);
        cp16(dB0 + p * BSTAGE_BYTES, bbase + (size_t)p * BSTAGE_H, 16);
        cp_commit();
    }

    int stage = 0, nstage = 2;
    for (int kt = 0; kt < NT; kt++) {
        cp_wait1();
        __syncthreads();
        if (kt + 2 < NT) {
            cp16(dA0 + nstage * AH_STAGE_BYTES, abase + (kt + 2) * 16, aok);
            cp16(dB0 + nstage * BSTAGE_BYTES, bbase + (size_t)(kt + 2) * BSTAGE_H, 16);
        }
        cp_commit();

        const __half* Ab = As + stage * AH_STAGE;
        const __half* Bb = Bs + stage * BSTAGE_H;

        uint32_t afr[4];
        {
            const uint32_t* ar1 = (const uint32_t*)(Ab + (w * 16 + g) * AH_PITCH);
            const uint32_t* ar2 = (const uint32_t*)(Ab + (w * 16 + g + 8) * AH_PITCH);
            afr[0] = ar1[t4];
            afr[1] = ar2[t4];
            afr[2] = ar1[t4 + 4];
            afr[3] = ar2[t4 + 4];
        }
#pragma unroll
        for (int nt = 0; nt < 16; nt++) {
            uint2 bq = *(const uint2*)(Bb + (nt * 8 + g) * 16 + t4 * 4);
            mma_f16(acc[nt], afr, bq.x, bq.y);
        }
        stage = (stage + 1 == 3) ? 0 : stage + 1;
        nstage = (nstage + 1 == 3) ? 0 : nstage + 1;
    }
}

// ---------------- proj gemm body ----------------
template <int KDIM, int NATT>
__device__ __forceinline__ void gemm_body(
        const float* __restrict__ X, const __half* __restrict__ Wh,
        const float* __restrict__ bias, __half* __restrict__ out,
        int Nrows, int bx, float* As, __half* Bs,
        const float* __restrict__ att0, float* __restrict__ ao0,
        const float* __restrict__ att1, float* __restrict__ ao1,
        const float* __restrict__ att2, float* __restrict__ ao2) {
    int tid = threadIdx.x, w = tid >> 5, lane = tid & 31;
    int g = lane >> 2, t4 = lane & 3;
    int row0 = bx * 128;

    int arow = tid >> 1;
    int garow = row0 + arow;
    int aok = (garow < Nrows) ? 16 : 0;
    const float* abase = X + (size_t)(aok ? garow : 0) * KDIM + (tid & 1) * 8;

    float acc[16][4];
#pragma unroll
    for (int nt = 0; nt < 16; nt++)
#pragma unroll
        for (int j = 0; j < 4; j++) acc[nt][j] = 0.f;

    gemm_mainloop<KDIM>(abase, aok, Wh, As, Bs, acc, tid, w, g, t4);

    int t2 = t4 * 2;
    int r1 = row0 + w * 16 + g;
    int r2 = r1 + 8;
#pragma unroll
    for (int nt = 0; nt < 16; nt++) {
        float2 bb = *(const float2*)(bias + nt * 8 + t2);
        acc[nt][0] += bb.x; acc[nt][1] += bb.y;
        acc[nt][2] += bb.x; acc[nt][3] += bb.y;
    }
#pragma unroll
    for (int nt = 0; nt < 16; nt++) {
        int col = nt * 8 + t2;
        if (r1 < Nrows)
            *(__half2*)(out + (size_t)r1 * CC + col) =
                __float22half2_rn(make_float2(acc[nt][0], acc[nt][1]));
        if (r2 < Nrows)
            *(__half2*)(out + (size_t)r2 * CC + col) =
                __float22half2_rn(make_float2(acc[nt][2], acc[nt][3]));
    }
    alpha_epilogue(acc, att0, ao0, r1, r2, Nrows, t4);
    if (NATT > 1) alpha_epilogue(acc, att1, ao1, r1, r2, Nrows, t4);
    if (NATT > 2) alpha_epilogue(acc, att2, ao2, r1, r2, Nrows, t4);
}

__device__ __forceinline__ void hist_body(const int* __restrict__ e_ap,
                                          const int* __restrict__ e_pp, int bx) {
    for (int idx = bx * 256 + threadIdx.x; idx < 2 * EE; idx += GH * 256) {
        int t = (idx >= EE);
        int e = idx - t * EE;
        const int* ed = t ? e_pp : e_ap;
        int dst = ed[EE + e];
        int r = atomicAdd(&g_cnt[t * NP + dst], 1);
        g_rank[idx] = r;
    }
}

// ---------------- phase1 (minBlocks=3 to lift occupancy) ----------------
__global__ __launch_bounds__(256, 3) void phase1_kernel(
        const float* __restrict__ xa, const float* __restrict__ ba,
        const float* __restrict__ xp, const float* __restrict__ bp,
        const float* __restrict__ att_src_ap, const float* __restrict__ att_dst_ap,
        const float* __restrict__ att_src_pp, const float* __restrict__ att_dst_pp,
        const int* __restrict__ e_ap, const int* __restrict__ e_pp) {
    __shared__ __align__(16) float As[3 * ASTAGE_FLOATS];
    __shared__ __align__(16) __half Bs[3 * BSTAGE_H];
    int bx = blockIdx.x;
    if (bx < GA) {
        gemm_body<FA, 1>(xa, g_Wah, ba, g_h_a, NA, bx, As, Bs,
                         att_src_ap, g_as_ap, 0, 0, 0, 0);
    } else if (bx < GA + GP) {
        gemm_body<FP, 3>(xp, g_Wph, bp, g_h_p, NP, bx - GA, As, Bs,
                         att_dst_ap, g_ad_ap, att_src_pp, g_as_pp,
                         att_dst_pp, g_ad_pp);
    } else {
        hist_body(e_ap, e_pp, bx - GA - GP);
    }
}

// ---------------- scan ----------------
#define SCAN_T 1024
#define SCAN_CHUNK 49
__global__ void scan_kernel() {
    int t = blockIdx.x;
    int tid = threadIdx.x;
    int lane = tid & 31, wid = tid >> 5;
    const int* cnt = g_cnt + t * NP;
    int* rowptr = g_rowptr + t * (NP + 1);

    int lo = tid * SCAN_CHUNK;
    int hi = lo + SCAN_CHUNK; if (hi > NP) hi = NP;
    int tsum = 0;
    for (int i = lo; i < hi; i++) tsum += cnt[i];

    int incl = tsum;
#pragma unroll
    for (int o = 1; o < 32; o <<= 1) {
        int v = __shfl_up_sync(0xFFFFFFFFu, incl, o);
        if (lane >= o) incl += v;
    }
    __shared__ int wtot[32];
    if (lane == 31) wtot[wid] = incl;
    __syncthreads();
    if (wid == 0) {
        int v = wtot[lane];
#pragma unroll
        for (int o = 1; o < 32; o <<= 1) {
            int u = __shfl_up_sync(0xFFFFFFFFu, v, o);
            if (lane >= o) v += u;
        }
        wtot[lane] = v;
    }
    __syncthreads();
    int running = (wid ? wtot[wid - 1] : 0) + incl - tsum;
    for (int i = lo; i < hi; i++) {
        rowptr[i] = running;
        running += cnt[i];
    }
    if (tid == 0) rowptr[NP] = EE;
}

// ---------------- scatter (2 edges/thread) ----------------
__global__ void scatter_kernel(const int* __restrict__ e_ap,
                               const int* __restrict__ e_pp) {
    int base2 = (blockIdx.x * blockDim.x + threadIdx.x) * 2;
#pragma unroll
    for (int j = 0; j < 2; j++) {
        int idx = base2 + j;
        if (idx >= 2 * EE) return;
        int t = (idx >= EE);
        int e = idx - t * EE;
        const int* ed = t ? e_pp : e_ap;
        int src = ed[e];
        int dst = ed[EE + e];
        int pos = g_rowptr[t * (NP + 1) + dst] + g_rank[idx];
        g_srcs[(size_t)t * EE + pos] = src;
    }
}

// ---------------- edge kernel (512 threads; fp16 in/out) ----------------
__global__ __launch_bounds__(512) void edge_kernel() {
    __shared__ int   sh_s[16][32];
    __shared__ float sh_e[16][32][8];
    int warp = threadIdx.x >> 5;
    int lane = threadIdx.x & 31;
    int gw = blockIdx.x * 16 + warp;
    if (gw >= 2 * NP) return;
    int t = (gw >= NP);
    int dst = gw - t * NP;

    const int* rowptr = g_rowptr + t * (NP + 1);
    const int* srcs = g_srcs + (size_t)t * EE;
    const float* as = t ? g_as_pp : g_as_ap;
    const float* ad = t ? g_ad_pp : g_ad_ap;
    const __half* Hsrc = t ? g_h_p : g_h_a;
    __half* outp = g_out01 + (size_t)t * NP * CC;

    int base = rowptr[dst];
    int deg = rowptr[dst + 1] - base;

    __half* ow = outp + (size_t)dst * CC;
    if (deg == 0) {
        *(uint2*)(ow + lane * 4) = make_uint2(0u, 0u);
        return;
    }

    float4 ad0 = *(const float4*)(ad + dst * HH);
    float4 ad1 = *(const float4*)(ad + dst * HH + 4);
    float advs[8] = {ad0.x, ad0.y, ad0.z, ad0.w, ad1.x, ad1.y, ad1.z, ad1.w};

    int myh = lane >> 2;
    float4 acc = make_float4(0.f, 0.f, 0.f, 0.f);
    float denom = 0.f;

    for (int chunk = 0; chunk < deg; chunk += 32) {
        int n = min(32, deg - chunk);
        if (lane < n) {
            int s = srcs[base + chunk + lane];
            sh_s[warp][lane] = s;
            float4 a0 = *(const float4*)(as + s * HH);
            float4 a1 = *(const float4*)(as + s * HH + 4);
            float al[8] = {a0.x, a0.y, a0.z, a0.w, a1.x, a1.y, a1.z, a1.w};
            float e[8];
#pragma unroll
            for (int h = 0; h < 8; h++) {
                float v = al[h] + advs[h];
                v = (v >= 0.f) ? v : 0.2f * v;
                e[h] = __expf(v);
            }
            *(float4*)&sh_e[warp][lane][0] = make_float4(e[0], e[1], e[2], e[3]);
            *(float4*)&sh_e[warp][lane][4] = make_float4(e[4], e[5], e[6], e[7]);
        }
        __syncwarp();
#pragma unroll 4
        for (int i = 0; i < n; i++) {
            int s = sh_s[warp][i];
            float wgt = sh_e[warp][i][myh];
            uint2 hv = *(const uint2*)(Hsrc + (size_t)s * CC + lane * 4);
            float2 f01 = __half22float2(*(const __half2*)&hv.x);
            float2 f23 = __half22float2(*(const __half2*)&hv.y);
            denom += wgt;
            acc.x += wgt * f01.x; acc.y += wgt * f01.y;
            acc.z += wgt * f23.x; acc.w += wgt * f23.y;
        }
        __syncwarp();
    }
    float inv = 1.f / denom;
    __half2 h01 = __float22half2_rn(make_float2(fmaxf(acc.x * inv, 0.f),
                                                fmaxf(acc.y * inv, 0.f)));
    __half2 h23 = __float22half2_rn(make_float2(fmaxf(acc.z * inv, 0.f),
                                                fmaxf(acc.w * inv, 0.f)));
    uint2 st;
    st.x = *(uint32_t*)&h01;
    st.y = *(uint32_t*)&h23;
    *(uint2*)(ow + lane * 4) = st;
}

// ---------------- phase5 bodies ----------------
__device__ __forceinline__ void semantic_body(
        const float* __restrict__ kb, const float* __restrict__ q,
        int rsel, int bx, __half* As, __half* Bs, float* red) {
    const __half* X = g_out01 + (size_t)rsel * NP * CC;
    int tid = threadIdx.x, w = tid >> 5, lane = tid & 31;
    int g = lane >> 2, t4 = lane & 3;
    int row0 = bx * 128;

    int arow = tid >> 1;
    int garow = row0 + arow;
    int aok = (garow < NP) ? 16 : 0;
    const __half* abase = X + (size_t)(aok ? garow : 0) * CC + (tid & 1) * 8;

    float acc[16][4];
#pragma unroll
    for (int nt = 0; nt < 16; nt++)
#pragma unroll
        for (int j = 0; j < 4; j++) acc[nt][j] = 0.f;

    gemm_mainloop_h(abase, aok, g_kWh, As, Bs, acc, tid, w, g, t4);

    int t2 = t4 * 2;
    int r1 = row0 + w * 16 + g;
    int r2 = r1 + 8;
    float part = 0.f;
#pragma unroll
    for (int nt = 0; nt < 16; nt++) {
        int col = nt * 8 + t2;
        float2 kb2 = *(const float2*)(kb + col);
        float2 q2 = *(const float2*)(q + col);
        if (r1 < NP)
            part += tanh_fast(acc[nt][0] + kb2.x) * q2.x
                  + tanh_fast(acc[nt][1] + kb2.y) * q2.y;
        if (r2 < NP)
            part += tanh_fast(acc[nt][2] + kb2.x) * q2.x
                  + tanh_fast(acc[nt][3] + kb2.y) * q2.y;
    }
#pragma unroll
    for (int o = 16; o; o >>= 1) part += __shfl_xor_sync(0xFFFFFFFFu, part, o);
    if (lane == 0) red[w] = part;
    __syncthreads();
    if (tid == 0) {
        float s = 0.f;
#pragma unroll
        for (int i = 0; i < 8; i++) s += red[i];
        atomicAdd(&g_wsum[rsel], s);
    }
}

#define STAT_ROWS 512
__device__ __forceinline__ void stats5_body(int bx) {
    int tid = threadIdx.x;
    int cp = tid & 63;
    int rq = tid >> 6;
    const __half2* o0 = (const __half2*)g_out01;
    const __half2* o1 = (const __half2*)(g_out01 + (size_t)NP * CC);
    int r0 = bx * STAT_ROWS + rq;
    int r1 = bx * STAT_ROWS + STAT_ROWS; if (r1 > NP) r1 = NP;
    float sa0 = 0.f, sa1 = 0.f, sb0 = 0.f, sb1 = 0.f;
    float saa0 = 0.f, saa1 = 0.f, sbb0 = 0.f, sbb1 = 0.f, sab0 = 0.f, sab1 = 0.f;
    for (int r = r0; r < r1; r += 4) {
        float2 a = __half22float2(o0[(size_t)r * 64 + cp]);
        float2 b = __half22float2(o1[(size_t)r * 64 + cp]);
        sa0 += a.x; sa1 += a.y; sb0 += b.x; sb1 += b.y;
        saa0 += a.x * a.x; saa1 += a.y * a.y;
        sbb0 += b.x * b.x; sbb1 += b.y * b.y;
        sab0 += a.x * b.x; sab1 += a.y * b.y;
    }
    int c0 = cp * 2, c1 = c0 + 1;
    atomicAdd(&g_Sa[c0], sa0);  atomicAdd(&g_Sa[c1], sa1);
    atomicAdd(&g_Sb[c0], sb0);  atomicAdd(&g_Sb[c1], sb1);
    atomicAdd(&g_Saa[c0], saa0); atomicAdd(&g_Saa[c1], saa1);
    atomicAdd(&g_Sbb[c0], sbb0); atomicAdd(&g_Sbb[c1], sbb1);
    atomicAdd(&g_Sab[c0], sab0); atomicAdd(&g_Sab[c1], sab1);
}

// ---------------- phase5 (minBlocks=3) ----------------
__global__ __launch_bounds__(256, 3) void phase5_kernel(
        const float* __restrict__ kb, const float* __restrict__ q) {
    __shared__ __align__(16) __half As[3 * AH_STAGE];
    __shared__ __align__(16) __half Bs[3 * BSTAGE_H];
    __shared__ float red[8];
    int bx = blockIdx.x;
    if (bx < GSEM) {
        int rsel = (bx >= GSEM / 2);
        semantic_body(kb, q, rsel, bx - rsel * (GSEM / 2), As, Bs, red);
    } else {
        stats5_body(bx - GSEM);
    }
}

// ---------------- final ----------------
__global__ __launch_bounds__(256) void final_kernel(
        const float* __restrict__ norm_w, const float* __restrict__ norm_b,
        const float* __restrict__ norm_ms,
        const float* __restrict__ linW, const float* __restrict__ linb,
        float* __restrict__ y) {
    __shared__ float rowbuf[16][CC];
    __shared__ float lw[CC * OUTC];
    __shared__ float lb[OUTC];
    __shared__ float snA[CC], snB[CC];
    int tid = threadIdx.x;

    float w0 = g_wsum[0] * (1.f / NP);
    float w1 = g_wsum[1] * (1.f / NP);
    float m = fmaxf(w0, w1);
    float e0 = expf(w0 - m), e1 = expf(w1 - m);
    float ssum = e0 + e1;
    float b0 = e0 / ssum, b1 = e1 / ssum;

    for (int i = tid; i < CC * OUTC; i += 256) lw[i] = linW[i];
    if (tid < OUTC) lb[tid] = linb[tid];
    if (tid < CC) {
        int c = tid;
        float mean = (b0 * g_Sa[c] + b1 * g_Sb[c]) * (1.f / NP);
        float eo2 = (b0 * b0 * g_Saa[c] + 2.f * b0 * b1 * g_Sab[c]
                     + b1 * b1 * g_Sbb[c]) * (1.f / NP);
        float mm = mean * norm_ms[c];
        float var = eo2 - 2.f * mm * mean + mm * mm;
        float A = norm_w[c] * rsqrtf(var + EPSV);
        snA[c] = A;
        snB[c] = norm_b[c] - mm * A;
    }
    __syncthreads();

    const __half2* o0 = (const __half2*)g_out01;
    const __half2* o1 = (const __half2*)(g_out01 + (size_t)NP * CC);
    int nrow0 = blockIdx.x * 16;
#pragma unroll
    for (int j = 0; j < 4; j++) {
        int i = tid + j * 256;
        int r = i >> 6, cp = i & 63;
        int gr = nrow0 + r;
        float vx = 0.f, vy = 0.f;
        if (gr < NP) {
            float2 a = __half22float2(o0[(size_t)gr * 64 + cp]);
            float2 b = __half22float2(o1[(size_t)gr * 64 + cp]);
            int c0 = cp * 2;
            vx = (b0 * a.x + b1 * b.x) * snA[c0] + snB[c0];
            vy = (b0 * a.y + b1 * b.y) * snA[c0 + 1] + snB[c0 + 1];
        }
        rowbuf[r][cp * 2] = vx;
        rowbuf[r][cp * 2 + 1] = vy;
    }
    __syncthreads();
    int r = tid >> 4, o = tid & 15;
    int gr = nrow0 + r;
    if (gr < NP) {
        float s = lb[o];
#pragma unroll
        for (int c = 0; c < CC; c++) s += rowbuf[r][c] * lw[c * OUTC + o];
        y[(size_t)gr * OUTC + o] = s;
    }
}

// ---------------- launch ----------------
extern "C" void kernel_launch(void* const* d_in, const int* in_sizes, int n_in,
                              void* d_out, int out_size) {
    const float* x_author = (const float*)d_in[0];
    const float* x_paper  = (const float*)d_in[1];
    const float* W_a      = (const float*)d_in[2];
    const float* b_a      = (const float*)d_in[3];
    const float* W_p      = (const float*)d_in[4];
    const float* b_p      = (const float*)d_in[5];
    const float* att_src_ap = (const float*)d_in[6];
    const float* att_dst_ap = (const float*)d_in[7];
    const float* att_src_pp = (const float*)d_in[8];
    const float* att_dst_pp = (const float*)d_in[9];
    const float* k_W      = (const float*)d_in[10];
    const float* k_b      = (const float*)d_in[11];
    const float* q        = (const float*)d_in[12];
    const float* norm_w   = (const float*)d_in[13];
    const float* norm_b   = (const float*)d_in[14];
    const float* norm_ms  = (const float*)d_in[15];
    const float* lin_W    = (const float*)d_in[16];
    const float* lin_b    = (const float*)d_in[17];
    const int*   edge_ap  = (const int*)d_in[18];
    const int*   edge_pp  = (const int*)d_in[19];
    float* y = (float*)d_out;

    // 0. init
    init_kernel<<<256, 256>>>(W_a, W_p, k_W);

    // 1. gemm_a(+alpha) | gemm_p(+3 alphas) | hist(+rank)
    phase1_kernel<<<GA + GP + GH, 256>>>(x_author, b_a, x_paper, b_p,
                                         att_src_ap, att_dst_ap,
                                         att_src_pp, att_dst_pp,
                                         edge_ap, edge_pp);

    // 2. prefix scan
    scan_kernel<<<2, SCAN_T>>>();

    // 3. scatter (atomic-free, 2 edges/thread)
    scatter_kernel<<<(EE + 255) / 256, 256>>>(edge_ap, edge_pp);

    // 4. fused edge softmax + aggregation (512-thread blocks)
    edge_kernel<<<(2 * NP + 15) / 16, 512>>>();

    // 5. semantic gemms | stats
    phase5_kernel<<<GSEM + GST, 256>>>(k_b, q);

    // 6. normalize + classify
    final_kernel<<<(NP + 15) / 16, 256>>>(norm_w, norm_b, norm_ms,
                                          lin_W, lin_b, y);
}

// round 15
// speedup vs baseline: 1.0527x; 1.0527x over previous
#include <cuda_runtime.h>
#include <cuda_fp16.h>
#include <math.h>
#include <stdint.h>

#define NA 50000
#define NP 50000
#define EE 600000
#define HH 8
#define DD 16
#define CC 128
#define OUTC 16
#define FA 256
#define FP 128
#define EPSV 1e-5f

// ---------------- device scratch ----------------
__device__ __half   g_h_a[(size_t)NA * CC];       // fp16 projected features
__device__ __half   g_h_p[(size_t)NP * CC];
__device__ float    g_as_ap[NA * HH];
__device__ float    g_ad_ap[NP * HH];
__device__ float    g_as_pp[NP * HH];
__device__ float    g_ad_pp[NP * HH];
__device__ int      g_cnt[2 * NP];
__device__ int      g_rank[2 * (size_t)EE];
__device__ int      g_rowptr[2 * (NP + 1)];
__device__ int      g_srcs[2 * (size_t)EE];
__device__ __half   g_out01[2 * (size_t)NP * CC]; // fp16, relu-applied
__device__ __half   g_Wah[FA * CC];               // fragment-permuted fp16 weights
__device__ __half   g_Wph[FP * CC];
__device__ __half   g_kWh[CC * CC];
__device__ float    g_wsum[2];
__device__ float    g_Sa[CC], g_Sb[CC], g_Saa[CC], g_Sbb[CC], g_Sab[CC];

// ---------------- helpers ----------------
__device__ __forceinline__ float tanh_fast(float x) {
    float y;
    asm("tanh.approx.f32 %0, %1;" : "=f"(y) : "f"(x));
    return y;
}
__device__ __forceinline__ uint32_t packh2(float lo, float hi) {
    __half2 h = __float22half2_rn(make_float2(lo, hi));
    return *(uint32_t*)&h;
}
__device__ __forceinline__ void mma_f16(float* c, const uint32_t* a,
                                        uint32_t b0, uint32_t b1) {
    asm("mma.sync.aligned.m16n8k16.row.col.f32.f16.f16.f32 "
        "{%0,%1,%2,%3},{%4,%5,%6,%7},{%8,%9},{%0,%1,%2,%3};"
        : "+f"(c[0]), "+f"(c[1]), "+f"(c[2]), "+f"(c[3])
        : "r"(a[0]), "r"(a[1]), "r"(a[2]), "r"(a[3]), "r"(b0), "r"(b1));
}
__device__ __forceinline__ void cp16(uint32_t dst, const void* src, int sz) {
    asm volatile("cp.async.ca.shared.global [%0], [%1], 16, %2;"
                 :: "r"(dst), "l"(src), "r"(sz));
}
__device__ __forceinline__ void cp_commit() { asm volatile("cp.async.commit_group;"); }
__device__ __forceinline__ void cp_wait1()  { asm volatile("cp.async.wait_group 1;"); }

#define APITCH 20
#define ASTAGE_FLOATS (128 * APITCH)          // fp32 A stage (phase1)
#define ASTAGE_BYTES  (ASTAGE_FLOATS * 4)
#define AH_PITCH 24
#define AH_STAGE  (128 * AH_PITCH)            // fp16 A stage (semantic), halves
#define AH_STAGE_BYTES (AH_STAGE * 2)
#define BSTAGE_H      2048
#define BSTAGE_BYTES  (BSTAGE_H * 2)

// grid partition constants
#define GA 391
#define GP 391
#define GH 1024
#define GSEM 782
#define GST 98

// ---------------- init ----------------
__device__ __forceinline__ void build_wh(const float* __restrict__ W,
                                         __half* __restrict__ Wh,
                                         int total, int idx, int stride) {
    for (int o = idx; o < total; o += stride) {
        int kt = o >> 11;
        int rem = o & 2047;
        int col = rem >> 4;
        int u = rem & 15;
        int t4 = u >> 2;
        int j = u & 3;
        int k = kt * 16 + 2 * t4 + (j & 1) + 8 * (j >> 1);
        Wh[o] = __float2half_rn(W[k * CC + col]);
    }
}

__global__ void init_kernel(const float* __restrict__ Wa,
                            const float* __restrict__ Wp,
                            const float* __restrict__ kW) {
    int idx = blockIdx.x * blockDim.x + threadIdx.x;
    int stride = gridDim.x * blockDim.x;
    for (int i = idx; i < 2 * NP; i += stride) g_cnt[i] = 0;
    build_wh(Wa, g_Wah, FA * CC, idx, stride);
    build_wh(Wp, g_Wph, FP * CC, idx, stride);
    build_wh(kW, g_kWh, CC * CC, idx, stride);
    if (idx < CC) {
        g_Sa[idx] = 0.f; g_Sb[idx] = 0.f;
        g_Saa[idx] = 0.f; g_Sbb[idx] = 0.f; g_Sab[idx] = 0.f;
    }
    if (idx < 2) g_wsum[idx] = 0.f;
}

// ---------------- alpha epilogue ----------------
__device__ __forceinline__ void alpha_epilogue(
        const float acc[16][4], const float* __restrict__ att,
        float* __restrict__ out, int r1, int r2, int Nrows, int t4) {
    int t2 = t4 * 2;
    float p1[8], p2[8];
#pragma unroll
    for (int h = 0; h < 8; h++) {
        int na = 2 * h, nb = 2 * h + 1;
        float2 aA = *(const float2*)(att + na * 8 + t2);
        float2 aB = *(const float2*)(att + nb * 8 + t2);
        p1[h] = acc[na][0] * aA.x + acc[na][1] * aA.y
              + acc[nb][0] * aB.x + acc[nb][1] * aB.y;
        p2[h] = acc[na][2] * aA.x + acc[na][3] * aA.y
              + acc[nb][2] * aB.x + acc[nb][3] * aB.y;
    }
#pragma unroll
    for (int h = 0; h < 8; h++) {
        p1[h] += __shfl_xor_sync(0xFFFFFFFFu, p1[h], 1);
        p1[h] += __shfl_xor_sync(0xFFFFFFFFu, p1[h], 2);
        p2[h] += __shfl_xor_sync(0xFFFFFFFFu, p2[h], 1);
        p2[h] += __shfl_xor_sync(0xFFFFFFFFu, p2[h], 2);
    }
#pragma unroll
    for (int h = 0; h < 8; h++) {
        if ((h & 3) == t4) {
            if (r1 < Nrows) out[r1 * 8 + h] = p1[h];
            if (r2 < Nrows) out[r2 * 8 + h] = p2[h];
        }
    }
}

// ---------------- fp32-A gemm mainloop (phase1) ----------------
template <int KDIM>
__device__ __forceinline__ void gemm_mainloop(
        const float* __restrict__ abase, int aok,
        const __half* __restrict__ Wh,
        float* As, __half* Bs, float acc[16][4],
        int tid, int w, int g, int t4) {
    const __half* bbase = Wh + tid * 8;
    int arow = tid >> 1, ak = (tid & 1) * 8;
    uint32_t dA0 = (uint32_t)__cvta_generic_to_shared(&As[arow * APITCH + ak]);
    uint32_t dB0 = (uint32_t)__cvta_generic_to_shared(&Bs[tid * 8]);
    const int NT = KDIM / 16;

#pragma unroll
    for (int p = 0; p < 2; p++) {
        const float* ap = abase + p * 16;
        const __half* bp = bbase + (size_t)p * BSTAGE_H;
        uint32_t dA = dA0 + p * ASTAGE_BYTES;
        uint32_t dB = dB0 + p * BSTAGE_BYTES;
        cp16(dA, ap, aok); cp16(dA + 16, ap + 4, aok);
        cp16(dB, bp, 16);
        cp_commit();
    }

    int stage = 0, nstage = 2;
    for (int kt = 0; kt < NT; kt++) {
        cp_wait1();
        __syncthreads();
        if (kt + 2 < NT) {
            const float* ap = abase + (kt + 2) * 16;
            const __half* bp = bbase + (size_t)(kt + 2) * BSTAGE_H;
            uint32_t dA = dA0 + nstage * ASTAGE_BYTES;
            uint32_t dB = dB0 + nstage * BSTAGE_BYTES;
            cp16(dA, ap, aok); cp16(dA + 16, ap + 4, aok);
            cp16(dB, bp, 16);
        }
        cp_commit();

        const float* Ab = As + stage * ASTAGE_FLOATS;
        const __half* Bb = Bs + stage * BSTAGE_H;

        uint32_t afr[4];
        {
            const float* ar1 = Ab + (w * 16 + g) * APITCH;
            const float* ar2 = Ab + (w * 16 + g + 8) * APITCH;
            float2 lo1 = *(const float2*)(ar1 + 2 * t4);
            float2 lo2 = *(const float2*)(ar2 + 2 * t4);
            float2 hi1 = *(const float2*)(ar1 + 2 * t4 + 8);
            float2 hi2 = *(const float2*)(ar2 + 2 * t4 + 8);
            afr[0] = packh2(lo1.x, lo1.y);
            afr[1] = packh2(lo2.x, lo2.y);
            afr[2] = packh2(hi1.x, hi1.y);
            afr[3] = packh2(hi2.x, hi2.y);
        }
#pragma unroll
        for (int nt = 0; nt < 16; nt++) {
            uint2 bq = *(const uint2*)(Bb + (nt * 8 + g) * 16 + t4 * 4);
            mma_f16(acc[nt], afr, bq.x, bq.y);
        }
        stage = (stage + 1 == 3) ? 0 : stage + 1;
        nstage = (nstage + 1 == 3) ? 0 : nstage + 1;
    }
}

// ---------------- fp16-A gemm mainloop (semantic) ----------------
__device__ __forceinline__ void gemm_mainloop_h(
        const __half* __restrict__ abase, int aok,
        const __half* __restrict__ Wh,
        __half* As, __half* Bs, float acc[16][4],
        int tid, int w, int g, int t4) {
    const __half* bbase = Wh + tid * 8;
    int arow = tid >> 1, ak = (tid & 1) * 8;
    uint32_t dA0 = (uint32_t)__cvta_generic_to_shared(&As[arow * AH_PITCH + ak]);
    uint32_t dB0 = (uint32_t)__cvta_generic_to_shared(&Bs[tid * 8]);
    const int NT = CC / 16;

#pragma unroll
    for (int p = 0; p < 2; p++) {
        cp16(dA0 + p * AH_STAGE_BYTES, abase + p * 16, aok);
        cp16(dB0 + p * BSTAGE_BYTES, bbase + (size_t)p * BSTAGE_H, 16);
        cp_commit();
    }

    int stage = 0, nstage = 2;
    for (int kt = 0; kt < NT; kt++) {
        cp_wait1();
        __syncthreads();
        if (kt + 2 < NT) {
            cp16(dA0 + nstage * AH_STAGE_BYTES, abase + (kt + 2) * 16, aok);
            cp16(dB0 + nstage * BSTAGE_BYTES, bbase + (size_t)(kt + 2) * BSTAGE_H, 16);
        }
        cp_commit();

        const __half* Ab = As + stage * AH_STAGE;
        const __half* Bb = Bs + stage * BSTAGE_H;

        uint32_t afr[4];
        {
            const uint32_t* ar1 = (const uint32_t*)(Ab + (w * 16 + g) * AH_PITCH);
            const uint32_t* ar2 = (const uint32_t*)(Ab + (w * 16 + g + 8) * AH_PITCH);
            afr[0] = ar1[t4];
            afr[1] = ar2[t4];
            afr[2] = ar1[t4 + 4];
            afr[3] = ar2[t4 + 4];
        }
#pragma unroll
        for (int nt = 0; nt < 16; nt++) {
            uint2 bq = *(const uint2*)(Bb + (nt * 8 + g) * 16 + t4 * 4);
            mma_f16(acc[nt], afr, bq.x, bq.y);
        }
        stage = (stage + 1 == 3) ? 0 : stage + 1;
        nstage = (nstage + 1 == 3) ? 0 : nstage + 1;
    }
}

// ---------------- proj gemm body ----------------
template <int KDIM, int NATT>
__device__ __forceinline__ void gemm_body(
        const float* __restrict__ X, const __half* __restrict__ Wh,
        const float* __restrict__ bias, __half* __restrict__ out,
        int Nrows, int bx, float* As, __half* Bs,
        const float* __restrict__ att0, float* __restrict__ ao0,
        const float* __restrict__ att1, float* __restrict__ ao1,
        const float* __restrict__ att2, float* __restrict__ ao2) {
    int tid = threadIdx.x, w = tid >> 5, lane = tid & 31;
    int g = lane >> 2, t4 = lane & 3;
    int row0 = bx * 128;

    int arow = tid >> 1;
    int garow = row0 + arow;
    int aok = (garow < Nrows) ? 16 : 0;
    const float* abase = X + (size_t)(aok ? garow : 0) * KDIM + (tid & 1) * 8;

    float acc[16][4];
#pragma unroll
    for (int nt = 0; nt < 16; nt++)
#pragma unroll
        for (int j = 0; j < 4; j++) acc[nt][j] = 0.f;

    gemm_mainloop<KDIM>(abase, aok, Wh, As, Bs, acc, tid, w, g, t4);

    int t2 = t4 * 2;
    int r1 = row0 + w * 16 + g;
    int r2 = r1 + 8;
#pragma unroll
    for (int nt = 0; nt < 16; nt++) {
        float2 bb = *(const float2*)(bias + nt * 8 + t2);
        acc[nt][0] += bb.x; acc[nt][1] += bb.y;
        acc[nt][2] += bb.x; acc[nt][3] += bb.y;
    }
#pragma unroll
    for (int nt = 0; nt < 16; nt++) {
        int col = nt * 8 + t2;
        if (r1 < Nrows)
            *(__half2*)(out + (size_t)r1 * CC + col) =
                __float22half2_rn(make_float2(acc[nt][0], acc[nt][1]));
        if (r2 < Nrows)
            *(__half2*)(out + (size_t)r2 * CC + col) =
                __float22half2_rn(make_float2(acc[nt][2], acc[nt][3]));
    }
    alpha_epilogue(acc, att0, ao0, r1, r2, Nrows, t4);
    if (NATT > 1) alpha_epilogue(acc, att1, ao1, r1, r2, Nrows, t4);
    if (NATT > 2) alpha_epilogue(acc, att2, ao2, r1, r2, Nrows, t4);
}

__device__ __forceinline__ void hist_body(const int* __restrict__ e_ap,
                                          const int* __restrict__ e_pp, int bx) {
    for (int idx = bx * 256 + threadIdx.x; idx < 2 * EE; idx += GH * 256) {
        int t = (idx >= EE);
        int e = idx - t * EE;
        const int* ed = t ? e_pp : e_ap;
        int dst = ed[EE + e];
        int r = atomicAdd(&g_cnt[t * NP + dst], 1);
        g_rank[idx] = r;
    }
}

// ---------------- phase1 ----------------
__global__ __launch_bounds__(256) void phase1_kernel(
        const float* __restrict__ xa, const float* __restrict__ ba,
        const float* __restrict__ xp, const float* __restrict__ bp,
        const float* __restrict__ att_src_ap, const float* __restrict__ att_dst_ap,
        const float* __restrict__ att_src_pp, const float* __restrict__ att_dst_pp,
        const int* __restrict__ e_ap, const int* __restrict__ e_pp) {
    __shared__ __align__(16) float As[3 * ASTAGE_FLOATS];
    __shared__ __align__(16) __half Bs[3 * BSTAGE_H];
    int bx = blockIdx.x;
    if (bx < GA) {
        gemm_body<FA, 1>(xa, g_Wah, ba, g_h_a, NA, bx, As, Bs,
                         att_src_ap, g_as_ap, 0, 0, 0, 0);
    } else if (bx < GA + GP) {
        gemm_body<FP, 3>(xp, g_Wph, bp, g_h_p, NP, bx - GA, As, Bs,
                         att_dst_ap, g_ad_ap, att_src_pp, g_as_pp,
                         att_dst_pp, g_ad_pp);
    } else {
        hist_body(e_ap, e_pp, bx - GA - GP);
    }
}

// ---------------- scan ----------------
#define SCAN_T 1024
#define SCAN_CHUNK 49
__global__ void scan_kernel() {
    int t = blockIdx.x;
    int tid = threadIdx.x;
    int lane = tid & 31, wid = tid >> 5;
    const int* cnt = g_cnt + t * NP;
    int* rowptr = g_rowptr + t * (NP + 1);

    int lo = tid * SCAN_CHUNK;
    int hi = lo + SCAN_CHUNK; if (hi > NP) hi = NP;
    int tsum = 0;
    for (int i = lo; i < hi; i++) tsum += cnt[i];

    int incl = tsum;
#pragma unroll
    for (int o = 1; o < 32; o <<= 1) {
        int v = __shfl_up_sync(0xFFFFFFFFu, incl, o);
        if (lane >= o) incl += v;
    }
    __shared__ int wtot[32];
    if (lane == 31) wtot[wid] = incl;
    __syncthreads();
    if (wid == 0) {
        int v = wtot[lane];
#pragma unroll
        for (int o = 1; o < 32; o <<= 1) {
            int u = __shfl_up_sync(0xFFFFFFFFu, v, o);
            if (lane >= o) v += u;
        }
        wtot[lane] = v;
    }
    __syncthreads();
    int running = (wid ? wtot[wid - 1] : 0) + incl - tsum;
    for (int i = lo; i < hi; i++) {
        rowptr[i] = running;
        running += cnt[i];
    }
    if (tid == 0) rowptr[NP] = EE;
}

// ---------------- scatter ----------------
__global__ void scatter_kernel(const int* __restrict__ e_ap,
                               const int* __restrict__ e_pp) {
    int idx = blockIdx.x * blockDim.x + threadIdx.x;
    if (idx >= 2 * EE) return;
    int t = (idx >= EE);
    int e = idx - t * EE;
    const int* ed = t ? e_pp : e_ap;
    int src = ed[e];
    int dst = ed[EE + e];
    int pos = g_rowptr[t * (NP + 1) + dst] + g_rank[idx];
    g_srcs[(size_t)t * EE + pos] = src;
}

// ---------------- edge kernel (fp16 gathers + fp16 out stores) ----------------
__global__ __launch_bounds__(256) void edge_kernel() {
    __shared__ int   sh_s[8][32];
    __shared__ float sh_e[8][32][8];
    int warp = threadIdx.x >> 5;
    int lane = threadIdx.x & 31;
    int gw = blockIdx.x * 8 + warp;
    if (gw >= 2 * NP) return;
    int t = (gw >= NP);
    int dst = gw - t * NP;

    const int* rowptr = g_rowptr + t * (NP + 1);
    const int* srcs = g_srcs + (size_t)t * EE;
    const float* as = t ? g_as_pp : g_as_ap;
    const float* ad = t ? g_ad_pp : g_ad_ap;
    const __half* Hsrc = t ? g_h_p : g_h_a;
    __half* outp = g_out01 + (size_t)t * NP * CC;

    int base = rowptr[dst];
    int deg = rowptr[dst + 1] - base;

    __half* ow = outp + (size_t)dst * CC;
    if (deg == 0) {
        *(uint2*)(ow + lane * 4) = make_uint2(0u, 0u);
        return;
    }

    float4 ad0 = *(const float4*)(ad + dst * HH);
    float4 ad1 = *(const float4*)(ad + dst * HH + 4);
    float advs[8] = {ad0.x, ad0.y, ad0.z, ad0.w, ad1.x, ad1.y, ad1.z, ad1.w};

    int myh = lane >> 2;
    float4 acc = make_float4(0.f, 0.f, 0.f, 0.f);
    float denom = 0.f;

    for (int chunk = 0; chunk < deg; chunk += 32) {
        int n = min(32, deg - chunk);
        if (lane < n) {
            int s = srcs[base + chunk + lane];
            sh_s[warp][lane] = s;
            float4 a0 = *(const float4*)(as + s * HH);
            float4 a1 = *(const float4*)(as + s * HH + 4);
            float al[8] = {a0.x, a0.y, a0.z, a0.w, a1.x, a1.y, a1.z, a1.w};
            float e[8];
#pragma unroll
            for (int h = 0; h < 8; h++) {
                float v = al[h] + advs[h];
                v = (v >= 0.f) ? v : 0.2f * v;
                e[h] = __expf(v);
            }
            *(float4*)&sh_e[warp][lane][0] = make_float4(e[0], e[1], e[2], e[3]);
            *(float4*)&sh_e[warp][lane][4] = make_float4(e[4], e[5], e[6], e[7]);
        }
        __syncwarp();
#pragma unroll 4
        for (int i = 0; i < n; i++) {
            int s = sh_s[warp][i];
            float wgt = sh_e[warp][i][myh];
            uint2 hv = *(const uint2*)(Hsrc + (size_t)s * CC + lane * 4);
            float2 f01 = __half22float2(*(const __half2*)&hv.x);
            float2 f23 = __half22float2(*(const __half2*)&hv.y);
            denom += wgt;
            acc.x += wgt * f01.x; acc.y += wgt * f01.y;
            acc.z += wgt * f23.x; acc.w += wgt * f23.y;
        }
        __syncwarp();
    }
    float inv = 1.f / denom;
    __half2 h01 = __float22half2_rn(make_float2(fmaxf(acc.x * inv, 0.f),
                                                fmaxf(acc.y * inv, 0.f)));
    __half2 h23 = __float22half2_rn(make_float2(fmaxf(acc.z * inv, 0.f),
                                                fmaxf(acc.w * inv, 0.f)));
    uint2 st;
    st.x = *(uint32_t*)&h01;
    st.y = *(uint32_t*)&h23;
    *(uint2*)(ow + lane * 4) = st;
}

// ---------------- phase5 bodies ----------------
__device__ __forceinline__ void semantic_body(
        const float* __restrict__ kb, const float* __restrict__ q,
        int rsel, int bx, __half* As, __half* Bs, float* red) {
    const __half* X = g_out01 + (size_t)rsel * NP * CC;
    int tid = threadIdx.x, w = tid >> 5, lane = tid & 31;
    int g = lane >> 2, t4 = lane & 3;
    int row0 = bx * 128;

    int arow = tid >> 1;
    int garow = row0 + arow;
    int aok = (garow < NP) ? 16 : 0;
    const __half* abase = X + (size_t)(aok ? garow : 0) * CC + (tid & 1) * 8;

    float acc[16][4];
#pragma unroll
    for (int nt = 0; nt < 16; nt++)
#pragma unroll
        for (int j = 0; j < 4; j++) acc[nt][j] = 0.f;

    gemm_mainloop_h(abase, aok, g_kWh, As, Bs, acc, tid, w, g, t4);

    int t2 = t4 * 2;
    int r1 = row0 + w * 16 + g;
    int r2 = r1 + 8;
    float part = 0.f;
#pragma unroll
    for (int nt = 0; nt < 16; nt++) {
        int col = nt * 8 + t2;
        float2 kb2 = *(const float2*)(kb + col);
        float2 q2 = *(const float2*)(q + col);
        if (r1 < NP)
            part += tanh_fast(acc[nt][0] + kb2.x) * q2.x
                  + tanh_fast(acc[nt][1] + kb2.y) * q2.y;
        if (r2 < NP)
            part += tanh_fast(acc[nt][2] + kb2.x) * q2.x
                  + tanh_fast(acc[nt][3] + kb2.y) * q2.y;
    }
#pragma unroll
    for (int o = 16; o; o >>= 1) part += __shfl_xor_sync(0xFFFFFFFFu, part, o);
    if (lane == 0) red[w] = part;
    __syncthreads();
    if (tid == 0) {
        float s = 0.f;
#pragma unroll
        for (int i = 0; i < 8; i++) s += red[i];
        atomicAdd(&g_wsum[rsel], s);
    }
}

#define STAT_ROWS 512
__device__ __forceinline__ void stats5_body(int bx) {
    int tid = threadIdx.x;
    int cp = tid & 63;
    int rq = tid >> 6;
    const __half2* o0 = (const __half2*)g_out01;
    const __half2* o1 = (const __half2*)(g_out01 + (size_t)NP * CC);
    int r0 = bx * STAT_ROWS + rq;
    int r1 = bx * STAT_ROWS + STAT_ROWS; if (r1 > NP) r1 = NP;
    float sa0 = 0.f, sa1 = 0.f, sb0 = 0.f, sb1 = 0.f;
    float saa0 = 0.f, saa1 = 0.f, sbb0 = 0.f, sbb1 = 0.f, sab0 = 0.f, sab1 = 0.f;
    for (int r = r0; r < r1; r += 4) {
        float2 a = __half22float2(o0[(size_t)r * 64 + cp]);
        float2 b = __half22float2(o1[(size_t)r * 64 + cp]);
        sa0 += a.x; sa1 += a.y; sb0 += b.x; sb1 += b.y;
        saa0 += a.x * a.x; saa1 += a.y * a.y;
        sbb0 += b.x * b.x; sbb1 += b.y * b.y;
        sab0 += a.x * b.x; sab1 += a.y * b.y;
    }
    int c0 = cp * 2, c1 = c0 + 1;
    atomicAdd(&g_Sa[c0], sa0);  atomicAdd(&g_Sa[c1], sa1);
    atomicAdd(&g_Sb[c0], sb0);  atomicAdd(&g_Sb[c1], sb1);
    atomicAdd(&g_Saa[c0], saa0); atomicAdd(&g_Saa[c1], saa1);
    atomicAdd(&g_Sbb[c0], sbb0); atomicAdd(&g_Sbb[c1], sbb1);
    atomicAdd(&g_Sab[c0], sab0); atomicAdd(&g_Sab[c1], sab1);
}

// ---------------- phase5 ----------------
__global__ __launch_bounds__(256) void phase5_kernel(
        const float* __restrict__ kb, const float* __restrict__ q) {
    __shared__ __align__(16) __half As[3 * AH_STAGE];
    __shared__ __align__(16) __half Bs[3 * BSTAGE_H];
    __shared__ float red[8];
    int bx = blockIdx.x;
    if (bx < GSEM) {
        int rsel = (bx >= GSEM / 2);
        semantic_body(kb, q, rsel, bx - rsel * (GSEM / 2), As, Bs, red);
    } else {
        stats5_body(bx - GSEM);
    }
}

// ---------------- final ----------------
__global__ __launch_bounds__(256) void final_kernel(
        const float* __restrict__ norm_w, const float* __restrict__ norm_b,
        const float* __restrict__ norm_ms,
        const float* __restrict__ linW, const float* __restrict__ linb,
        float* __restrict__ y) {
    __shared__ float rowbuf[16][CC];
    __shared__ float lw[CC * OUTC];
    __shared__ float lb[OUTC];
    __shared__ float snA[CC], snB[CC];
    int tid = threadIdx.x;

    float w0 = g_wsum[0] * (1.f / NP);
    float w1 = g_wsum[1] * (1.f / NP);
    float m = fmaxf(w0, w1);
    float e0 = expf(w0 - m), e1 = expf(w1 - m);
    float ssum = e0 + e1;
    float b0 = e0 / ssum, b1 = e1 / ssum;

    for (int i = tid; i < CC * OUTC; i += 256) lw[i] = linW[i];
    if (tid < OUTC) lb[tid] = linb[tid];
    if (tid < CC) {
        int c = tid;
        float mean = (b0 * g_Sa[c] + b1 * g_Sb[c]) * (1.f / NP);
        float eo2 = (b0 * b0 * g_Saa[c] + 2.f * b0 * b1 * g_Sab[c]
                     + b1 * b1 * g_Sbb[c]) * (1.f / NP);
        float mm = mean * norm_ms[c];
        float var = eo2 - 2.f * mm * mean + mm * mm;
        float A = norm_w[c] * rsqrtf(var + EPSV);
        snA[c] = A;
        snB[c] = norm_b[c] - mm * A;
    }
    __syncthreads();

    const __half2* o0 = (const __half2*)g_out01;
    const __half2* o1 = (const __half2*)(g_out01 + (size_t)NP * CC);
    int nrow0 = blockIdx.x * 16;
#pragma unroll
    for (int j = 0; j < 4; j++) {
        int i = tid + j * 256;
        int r = i >> 6, cp = i & 63;
        int gr = nrow0 + r;
        float vx = 0.f, vy = 0.f;
        if (gr < NP) {
            float2 a = __half22float2(o0[(size_t)gr * 64 + cp]);
            float2 b = __half22float2(o1[(size_t)gr * 64 + cp]);
            int c0 = cp * 2;
            vx = (b0 * a.x + b1 * b.x) * snA[c0] + snB[c0];
            vy = (b0 * a.y + b1 * b.y) * snA[c0 + 1] + snB[c0 + 1];
        }
        rowbuf[r][cp * 2] = vx;
        rowbuf[r][cp * 2 + 1] = vy;
    }
    __syncthreads();
    int r = tid >> 4, o = tid & 15;
    int gr = nrow0 + r;
    if (gr < NP) {
        float s = lb[o];
#pragma unroll
        for (int c = 0; c < CC; c++) s += rowbuf[r][c] * lw[c * OUTC + o];
        y[(size_t)gr * OUTC + o] = s;
    }
}

// ---------------- launch ----------------
extern "C" void kernel_launch(void* const* d_in, const int* in_sizes, int n_in,
                              void* d_out, int out_size) {
    const float* x_author = (const float*)d_in[0];
    const float* x_paper  = (const float*)d_in[1];
    const float* W_a      = (const float*)d_in[2];
    const float* b_a      = (const float*)d_in[3];
    const float* W_p      = (const float*)d_in[4];
    const float* b_p      = (const float*)d_in[5];
    const float* att_src_ap = (const float*)d_in[6];
    const float* att_dst_ap = (const float*)d_in[7];
    const float* att_src_pp = (const float*)d_in[8];
    const float* att_dst_pp = (const float*)d_in[9];
    const float* k_W      = (const float*)d_in[10];
    const float* k_b      = (const float*)d_in[11];
    const float* q        = (const float*)d_in[12];
    const float* norm_w   = (const float*)d_in[13];
    const float* norm_b   = (const float*)d_in[14];
    const float* norm_ms  = (const float*)d_in[15];
    const float* lin_W    = (const float*)d_in[16];
    const float* lin_b    = (const float*)d_in[17];
    const int*   edge_ap  = (const int*)d_in[18];
    const int*   edge_pp  = (const int*)d_in[19];
    float* y = (float*)d_out;

    // 0. init
    init_kernel<<<256, 256>>>(W_a, W_p, k_W);

    // 1. gemm_a(+alpha) | gemm_p(+3 alphas) | hist(+rank)
    phase1_kernel<<<GA + GP + GH, 256>>>(x_author, b_a, x_paper, b_p,
                                         att_src_ap, att_dst_ap,
                                         att_src_pp, att_dst_pp,
                                         edge_ap, edge_pp);

    // 2. prefix scan
    scan_kernel<<<2, SCAN_T>>>();

    // 3. scatter (atomic-free)
    scatter_kernel<<<(2 * EE + 255) / 256, 256>>>(edge_ap, edge_pp);

    // 4. fused edge softmax + aggregation (fp16 in/out)
    edge_kernel<<<(2 * NP + 7) / 8, 256>>>();

    // 5. semantic gemms (fp16 A) | stats (fp16 reads)
    phase5_kernel<<<GSEM + GST, 256>>>(k_b, q);

    // 6. normalize + classify
    final_kernel<<<(NP + 15) / 16, 256>>>(norm_w, norm_b, norm_ms,
                                          lin_W, lin_b, y);
}